// round 14
// baseline (speedup 1.0000x reference)
#include <cuda_runtime.h>
#include <cuda_bf16.h>
#include <cuda_fp8.h>
#include <cstdint>

#define MDIM 16384
#define KDIM 2048
#define NDIM 2048
#define KB   (KDIM / 128)   // 16 quant blocks along K

// Scratch: fp8 operands + per-block float scales + per-bm-group ready flags.
__device__ uint8_t g_x8[(size_t)MDIM * KDIM];   // 32 MiB
__device__ uint8_t g_w8[(size_t)NDIM * KDIM];   // 4 MiB
__device__ float   g_sa[(size_t)MDIM * KB];     // 1 MiB
__device__ int     g_flag[256];                 // one per 64-row bm-group

__device__ __forceinline__ float bf16_round(float f) {
    return __bfloat162float(__float2bfloat16(f));
}

// ---------------------------------------------------------------------------
// Quantize one 128-elem block cooperatively by 8 lanes (lane slice r=0..7
// owns 16 consecutive elems). Caller guarantees all 32 lanes of the warp run
// this with 8-lane-aligned groups (shfl xor 4/2/1 stays in-group).
// ---------------------------------------------------------------------------
__device__ __forceinline__ void quant_block_v2(const float* __restrict__ x,
                                               size_t b, int r) {
    const float4* px = (const float4*)(x + b * 128 + r * 16);
    float4 f4[4];
#pragma unroll
    for (int i = 0; i < 4; i++) f4[i] = px[i];

    float v[16];
    float amax = 0.f;
#pragma unroll
    for (int i = 0; i < 4; i++) {
        v[4 * i + 0] = bf16_round(f4[i].x);
        v[4 * i + 1] = bf16_round(f4[i].y);
        v[4 * i + 2] = bf16_round(f4[i].z);
        v[4 * i + 3] = bf16_round(f4[i].w);
#pragma unroll
        for (int q = 0; q < 4; q++)
            amax = fmaxf(amax, fabsf(v[4 * i + q]));
    }
#pragma unroll
    for (int o = 4; o; o >>= 1)
        amax = fmaxf(amax, __shfl_xor_sync(0xffffffffu, amax, o));

    float s = fmaxf(amax, 1e-4f) / 448.0f;
    int e; float m = frexpf(s, &e);                // s = m*2^e, m in [0.5,1)
    float s2 = (m == 0.5f) ? ldexpf(1.f, e - 1) : ldexpf(1.f, e);
    float inv = 1.f / s2;                          // exact (power of two)

    uint32_t pk[4];
#pragma unroll
    for (int i = 0; i < 4; i++) {
        __nv_fp8x2_storage_t lo = __nv_cvt_float2_to_fp8x2(
            make_float2(v[4 * i + 0] * inv, v[4 * i + 1] * inv),
            __NV_SATFINITE, __NV_E4M3);
        __nv_fp8x2_storage_t hi = __nv_cvt_float2_to_fp8x2(
            make_float2(v[4 * i + 2] * inv, v[4 * i + 3] * inv),
            __NV_SATFINITE, __NV_E4M3);
        pk[i] = (uint32_t)lo | ((uint32_t)hi << 16);
    }
    *(uint4*)(g_x8 + b * 128 + r * 16) = make_uint4(pk[0], pk[1], pk[2], pk[3]);
    if (r == 0) g_sa[b] = s2;
}

// ---------------------------------------------------------------------------
// Kernel A: weight fp8 cast (1024 CTAs) + flag reset (CTA 0). Runs serially
// before the GEMM; its completion also resets flags for every graph replay.
// ---------------------------------------------------------------------------
__global__ void quant_w_reset_kernel(const float* __restrict__ w) {
    if (blockIdx.x == 0 && threadIdx.x < 256) g_flag[threadIdx.x] = 0;
    const size_t t = (size_t)blockIdx.x * 256 + threadIdx.x;   // 0..262143
    const float4* pw = (const float4*)w + t * 4;
    uint32_t pk[4];
#pragma unroll
    for (int i = 0; i < 4; i++) {
        float4 w4 = pw[i];
        __nv_fp8x2_storage_t lo = __nv_cvt_float2_to_fp8x2(
            make_float2(w4.x, w4.y), __NV_SATFINITE, __NV_E4M3);
        __nv_fp8x2_storage_t hi = __nv_cvt_float2_to_fp8x2(
            make_float2(w4.z, w4.w), __NV_SATFINITE, __NV_E4M3);
        pk[i] = (uint32_t)lo | ((uint32_t)hi << 16);
    }
    *(uint4*)(g_w8 + t * 16) = make_uint4(pk[0], pk[1], pk[2], pk[3]);
}

// ---------------------------------------------------------------------------
// Fused quant+GEMM. GEMM config = round-10/12 best-measured:
// CTA 64x64, 256 thr, 8 warps (4m x 2n), warp tile 16x32, 3 CTAs/SM,
// 4-stage cp.async ring, ldmatrix.x4, two-level block-scale accumulation.
// NEW: blockIdx.x==0 CTA of each bm-group quantizes its 64 A-rows first and
// releases a flag; siblings acquire it. Quant thus pipelines under compute.
// ---------------------------------------------------------------------------
constexpr int BM = 64, BN = 64;
constexpr int STAGES = 4;
constexpr int ROWB = 128 + 16;                       // 144 B/row, conflict-free
constexpr int STAGE_BYTES = (BM + BN) * ROWB;        // 18432
constexpr int SMEM_TOTAL = STAGES * STAGE_BYTES;     // 73728

__device__ __forceinline__ void cp_async16(uint32_t dst, const void* src) {
    asm volatile("cp.async.cg.shared.global [%0], [%1], 16;\n" :: "r"(dst), "l"(src));
}
__device__ __forceinline__ void cp_commit() {
    asm volatile("cp.async.commit_group;\n" ::: "memory");
}
template <int N>
__device__ __forceinline__ void cp_wait() {
    asm volatile("cp.async.wait_group %0;\n" :: "n"(N) : "memory");
}
__device__ __forceinline__ void ldm_x4(uint32_t& r0, uint32_t& r1, uint32_t& r2, uint32_t& r3,
                                       uint32_t addr) {
    asm volatile("ldmatrix.sync.aligned.m8n8.x4.shared.b16 {%0,%1,%2,%3}, [%4];\n"
                 : "=r"(r0), "=r"(r1), "=r"(r2), "=r"(r3) : "r"(addr));
}
__device__ __forceinline__ void mma_fp8(float* c, const uint32_t* a, const uint32_t* b) {
    asm volatile("mma.sync.aligned.m16n8k32.row.col.f32.e4m3.e4m3.f32 "
                 "{%0,%1,%2,%3}, {%4,%5,%6,%7}, {%8,%9}, {%0,%1,%2,%3};\n"
                 : "+f"(c[0]), "+f"(c[1]), "+f"(c[2]), "+f"(c[3])
                 : "r"(a[0]), "r"(a[1]), "r"(a[2]), "r"(a[3]), "r"(b[0]), "r"(b[1]));
}

__global__ __launch_bounds__(256, 3) void gemm_kernel(float* __restrict__ C,
                                                      const float* __restrict__ sinv,
                                                      const float* __restrict__ x) {
    extern __shared__ uint8_t sm[];
    const int tid = threadIdx.x;
    const int lane = tid & 31;
    const int wid = tid >> 5;                 // 0..7
    const int ybm = blockIdx.y;
    const int bm = ybm * BM;
    const int bn = blockIdx.x * BN;
    const int wm = (wid & 3) * 16;            // 4 m-tiles of 16
    const int wn = (wid >> 2) * 32;           // 2 n-cols of 32

    // ---- producer/consumer handshake for this bm-group's A quant ----
    if (blockIdx.x == 0) {
        // quantize 1024 blocks = rows [bm, bm+64): 32 blocks per pass x 32
        const size_t b0 = (size_t)ybm * 1024;
        const int grp = tid >> 3, r = tid & 7;
#pragma unroll 4
        for (int it = 0; it < 32; it++)
            quant_block_v2(x, b0 + it * 32 + grp, r);
        __syncthreads();
        __threadfence();
        if (tid == 0) *(volatile int*)&g_flag[ybm] = 1;     // release
    } else {
        if (tid == 0) {
            volatile int* f = &g_flag[ybm];
            while (*f == 0) __nanosleep(64);
            __threadfence();                                 // acquire
        }
        __syncthreads();
    }

    const uint32_t sm_u32 = (uint32_t)__cvta_generic_to_shared(sm);

    // ---- per-thread loader pointers: 1024 chunks of 16B, 4 per thread ----
    const uint8_t* gsrc[4];
    uint32_t soff[4];
#pragma unroll
    for (int i = 0; i < 4; i++) {
        int c = tid + 256 * i;                // 0..1023
        if (c < BM * 8) {                     // A chunk
            int row = c >> 3, cc = c & 7;
            gsrc[i] = g_x8 + (size_t)(bm + row) * KDIM + cc * 16;
            soff[i] = (uint32_t)(row * ROWB + cc * 16);
        } else {                              // B chunk
            int cb = c - BM * 8;
            int row = cb >> 3, cc = cb & 7;
            gsrc[i] = g_w8 + (size_t)(bn + row) * KDIM + cc * 16;
            soff[i] = (uint32_t)(BM * ROWB + row * ROWB + cc * 16);
        }
    }
    auto load_stage = [&](int s, int kb) {
        uint32_t base = sm_u32 + (uint32_t)(s * STAGE_BYTES);
        uint32_t koff = (uint32_t)kb << 7;    // kb * 128 bytes
#pragma unroll
        for (int i = 0; i < 4; i++)
            cp_async16(base + soff[i], gsrc[i] + koff);
    };

    float master[4][4];
#pragma unroll
    for (int j = 0; j < 4; j++)
#pragma unroll
        for (int l = 0; l < 4; l++) master[j][l] = 0.f;

    load_stage(0, 0); cp_commit();
    load_stage(1, 1); cp_commit();
    load_stage(2, 2); cp_commit();

    const int la_row  = lane & 15;
    const int la_half = lane >> 4;
    const int lb_row  = ((lane >> 4) << 3) + (lane & 7);
    const int lb_half = (lane >> 3) & 1;
    const uint32_t aBase = (uint32_t)((wm + la_row) * ROWB + la_half * 16);
    const uint32_t bBase0 = (uint32_t)(BM * ROWB + (wn + lb_row) * ROWB + lb_half * 16);
    const uint32_t bBase1 = bBase0 + 16u * ROWB;
    const int gr = lane >> 2;

    const float* psa0 = g_sa + (size_t)(bm + wm + gr) * KB;   // rows c0,c1
    const float* psa1 = psa0 + 8 * KB;                        // rows c2,c3
    const float* psw  = sinv + (size_t)(bn >> 7) * KB;

    for (int kb = 0; kb < KB; kb++) {
        int rem = KB - 1 - kb;
        if (rem >= 2)      cp_wait<2>();
        else if (rem == 1) cp_wait<1>();
        else               cp_wait<0>();
        __syncthreads();
        if (kb + 3 < KB) { load_stage((kb + 3) & 3, kb + 3); cp_commit(); }

        const uint32_t st = sm_u32 + (uint32_t)((kb & 3) * STAGE_BYTES);

        float part[4][4];
#pragma unroll
        for (int j = 0; j < 4; j++)
#pragma unroll
            for (int l = 0; l < 4; l++) part[j][l] = 0.f;

#pragma unroll
        for (int ks = 0; ks < 4; ks++) {      // four k32 steps in BK=128
            const uint32_t k0 = (uint32_t)(ks * 32);
            uint32_t a[4];
            ldm_x4(a[0], a[1], a[2], a[3], st + aBase + k0);
#pragma unroll
            for (int p = 0; p < 2; p++) {
                uint32_t b[4];
                ldm_x4(b[0], b[1], b[2], b[3],
                       st + (p ? bBase1 : bBase0) + k0);
                mma_fp8(part[2 * p + 0], a, b + 0);
                mma_fp8(part[2 * p + 1], a, b + 2);
            }
        }

        float swk = __ldg(psw + kb);
        float f0 = __ldg(psa0 + kb) * swk;    // acc rows c0,c1
        float f1 = __ldg(psa1 + kb) * swk;    // acc rows c2,c3
#pragma unroll
        for (int nt = 0; nt < 4; nt++) {
            master[nt][0] += part[nt][0] * f0;
            master[nt][1] += part[nt][1] * f0;
            master[nt][2] += part[nt][2] * f1;
            master[nt][3] += part[nt][3] * f1;
        }
    }

    const int gid = lane >> 2, tig = lane & 3;
#pragma unroll
    for (int nt = 0; nt < 4; nt++) {
        int row = bm + wm + gid;
        int col = bn + wn + nt * 8 + tig * 2;
        float2 v01 = make_float2(bf16_round(master[nt][0]), bf16_round(master[nt][1]));
        *(float2*)&C[(size_t)row * NDIM + col] = v01;
        float2 v23 = make_float2(bf16_round(master[nt][2]), bf16_round(master[nt][3]));
        *(float2*)&C[(size_t)(row + 8) * NDIM + col] = v23;
    }
}

// ---------------------------------------------------------------------------
// Inputs identified BY ELEMENT COUNT: x 33554432, weight 4194304, sinv 256.
// ---------------------------------------------------------------------------
extern "C" void kernel_launch(void* const* d_in, const int* in_sizes, int n_in,
                              void* d_out, int out_size) {
    const float* x = nullptr; const float* w = nullptr; const float* sinv = nullptr;
    for (int i = 0; i < n_in; i++) {
        long long sz = in_sizes[i];
        if (sz == (long long)MDIM * KDIM)      x    = (const float*)d_in[i];
        else if (sz == (long long)NDIM * KDIM) w    = (const float*)d_in[i];
        else                                   sinv = (const float*)d_in[i];
    }
    if (!x)    x    = (const float*)d_in[0];
    if (!w)    w    = (const float*)d_in[1];
    if (!sinv) sinv = (const float*)d_in[2];
    float* out = (float*)d_out;

    // 1) weight quant + flag reset (serial, ~4-5us)
    quant_w_reset_kernel<<<1024, 256>>>(w);

    // 2) fused A-quant + GEMM (quant pipelined under compute via flags)
    cudaFuncSetAttribute(gemm_kernel, cudaFuncAttributeMaxDynamicSharedMemorySize, SMEM_TOTAL);
    dim3 grid(NDIM / BN, MDIM / BM);               // (32, 256)
    gemm_kernel<<<grid, 256, SMEM_TOTAL>>>(out, sinv, x);
}

// round 15
// speedup vs baseline: 2.5700x; 2.5700x over previous
#include <cuda_runtime.h>
#include <cuda_bf16.h>
#include <cuda_fp8.h>
#include <cstdint>

#define MDIM 16384
#define KDIM 2048
#define NDIM 2048
#define KB   (KDIM / 128)   // 16 quant blocks along K

#define NGRP   256          // bm-groups of 64 rows
#define LEAD   14           // production lead distance (>= concurrent groups)

// Scratch: fp8 operands + per-block float scales + per-group done counters.
__device__ uint8_t g_x8[(size_t)MDIM * KDIM];   // 32 MiB
__device__ uint8_t g_w8[(size_t)NDIM * KDIM];   // 4 MiB
__device__ float   g_sa[(size_t)MDIM * KB];     // 1 MiB
__device__ int     g_cnt[NGRP];                 // quant-done counters

__device__ __forceinline__ float bf16_round(float f) {
    return __bfloat162float(__float2bfloat16(f));
}

// ---------------------------------------------------------------------------
// Quantize one 128-elem block cooperatively by 8 lanes (slice r owns 16
// consecutive elems). 8-lane xor reduction stays within the block's lanes.
// ---------------------------------------------------------------------------
__device__ __forceinline__ void quant_block_v2(const float* __restrict__ x,
                                               size_t b, int r) {
    const float4* px = (const float4*)(x + b * 128 + r * 16);
    float4 f4[4];
#pragma unroll
    for (int i = 0; i < 4; i++) f4[i] = px[i];

    float v[16];
    float amax = 0.f;
#pragma unroll
    for (int i = 0; i < 4; i++) {
        v[4 * i + 0] = bf16_round(f4[i].x);
        v[4 * i + 1] = bf16_round(f4[i].y);
        v[4 * i + 2] = bf16_round(f4[i].z);
        v[4 * i + 3] = bf16_round(f4[i].w);
#pragma unroll
        for (int q = 0; q < 4; q++)
            amax = fmaxf(amax, fabsf(v[4 * i + q]));
    }
#pragma unroll
    for (int o = 4; o; o >>= 1)
        amax = fmaxf(amax, __shfl_xor_sync(0xffffffffu, amax, o));

    float s = fmaxf(amax, 1e-4f) / 448.0f;
    int e; float m = frexpf(s, &e);                // s = m*2^e, m in [0.5,1)
    float s2 = (m == 0.5f) ? ldexpf(1.f, e - 1) : ldexpf(1.f, e);
    float inv = 1.f / s2;                          // exact (power of two)

    uint32_t pk[4];
#pragma unroll
    for (int i = 0; i < 4; i++) {
        __nv_fp8x2_storage_t lo = __nv_cvt_float2_to_fp8x2(
            make_float2(v[4 * i + 0] * inv, v[4 * i + 1] * inv),
            __NV_SATFINITE, __NV_E4M3);
        __nv_fp8x2_storage_t hi = __nv_cvt_float2_to_fp8x2(
            make_float2(v[4 * i + 2] * inv, v[4 * i + 3] * inv),
            __NV_SATFINITE, __NV_E4M3);
        pk[i] = (uint32_t)lo | ((uint32_t)hi << 16);
    }
    *(uint4*)(g_x8 + b * 128 + r * 16) = make_uint4(pk[0], pk[1], pk[2], pk[3]);
    if (r == 0) g_sa[b] = s2;
}

// ---------------------------------------------------------------------------
// Kernel A: weight fp8 cast (1024 CTAs) + counter reset (CTA 0). Serial,
// ~4us; the reset keeps every graph replay deterministic.
// ---------------------------------------------------------------------------
__global__ void quant_w_reset_kernel(const float* __restrict__ w) {
    if (blockIdx.x == 0 && threadIdx.x < NGRP) g_cnt[threadIdx.x] = 0;
    const size_t t = (size_t)blockIdx.x * 256 + threadIdx.x;   // 0..262143
    const float4* pw = (const float4*)w + t * 4;
    uint32_t pk[4];
#pragma unroll
    for (int i = 0; i < 4; i++) {
        float4 w4 = pw[i];
        __nv_fp8x2_storage_t lo = __nv_cvt_float2_to_fp8x2(
            make_float2(w4.x, w4.y), __NV_SATFINITE, __NV_E4M3);
        __nv_fp8x2_storage_t hi = __nv_cvt_float2_to_fp8x2(
            make_float2(w4.z, w4.w), __NV_SATFINITE, __NV_E4M3);
        pk[i] = (uint32_t)lo | ((uint32_t)hi << 16);
    }
    *(uint4*)(g_w8 + t * 16) = make_uint4(pk[0], pk[1], pk[2], pk[3]);
}

// ---------------------------------------------------------------------------
// Fused quant+GEMM. GEMM = round-10/12 best-measured config (CTA 64x64,
// 256 thr, 8 warps, warp tile 16x32, 3 CTAs/SM, 4-stage cp.async,
// ldmatrix.x4, two-level block-scale accumulation).
// Production: CTA (x,y) quantizes slice x of group y+LEAD (one wave ahead);
// CTAs with y<LEAD bootstrap their own group first. Per-group atomic
// counter; consumers spin (wait ~= 0 after wave 1).
// ---------------------------------------------------------------------------
constexpr int BM = 64, BN = 64;
constexpr int STAGES = 4;
constexpr int ROWB = 128 + 16;                       // 144 B/row, conflict-free
constexpr int STAGE_BYTES = (BM + BN) * ROWB;        // 18432
constexpr int SMEM_TOTAL = STAGES * STAGE_BYTES;     // 73728

__device__ __forceinline__ void cp_async16(uint32_t dst, const void* src) {
    asm volatile("cp.async.cg.shared.global [%0], [%1], 16;\n" :: "r"(dst), "l"(src));
}
__device__ __forceinline__ void cp_commit() {
    asm volatile("cp.async.commit_group;\n" ::: "memory");
}
template <int N>
__device__ __forceinline__ void cp_wait() {
    asm volatile("cp.async.wait_group %0;\n" :: "n"(N) : "memory");
}
__device__ __forceinline__ void ldm_x4(uint32_t& r0, uint32_t& r1, uint32_t& r2, uint32_t& r3,
                                       uint32_t addr) {
    asm volatile("ldmatrix.sync.aligned.m8n8.x4.shared.b16 {%0,%1,%2,%3}, [%4];\n"
                 : "=r"(r0), "=r"(r1), "=r"(r2), "=r"(r3) : "r"(addr));
}
__device__ __forceinline__ void mma_fp8(float* c, const uint32_t* a, const uint32_t* b) {
    asm volatile("mma.sync.aligned.m16n8k32.row.col.f32.e4m3.e4m3.f32 "
                 "{%0,%1,%2,%3}, {%4,%5,%6,%7}, {%8,%9}, {%0,%1,%2,%3};\n"
                 : "+f"(c[0]), "+f"(c[1]), "+f"(c[2]), "+f"(c[3])
                 : "r"(a[0]), "r"(a[1]), "r"(a[2]), "r"(a[3]), "r"(b[0]), "r"(b[1]));
}

__global__ __launch_bounds__(256, 3) void gemm_kernel(float* __restrict__ C,
                                                      const float* __restrict__ sinv,
                                                      const float* __restrict__ xin) {
    extern __shared__ uint8_t sm[];
    const int tid = threadIdx.x;
    const int lane = tid & 31;
    const int wid = tid >> 5;                 // 0..7
    const int xb = blockIdx.x;                // 0..31
    const int yb = blockIdx.y;                // 0..255
    const int bm = yb * BM;
    const int bn = xb * BN;
    const int wm = (wid & 3) * 16;            // 4 m-tiles of 16
    const int wn = (wid >> 2) * 32;           // 2 n-cols of 32

    // ================= distributed A-quant production =================
    {
        const int grp = tid >> 3, r = tid & 7;     // 32 blocks per CTA slice
        if (yb < LEAD) {                           // bootstrap own group
            quant_block_v2(xin, (size_t)yb * 1024 + xb * 32 + grp, r);
            __threadfence();
            __syncthreads();
            if (tid == 0) atomicAdd(&g_cnt[yb], 1);
        }
        const int g = yb + LEAD;                   // produce one wave ahead
        if (g < NGRP) {
            quant_block_v2(xin, (size_t)g * 1024 + xb * 32 + grp, r);
            __threadfence();
            __syncthreads();
            if (tid == 0) atomicAdd(&g_cnt[g], 1);
        }
        // consume: wait for own group complete
        if (tid == 0) {
            volatile int* c = &g_cnt[yb];
            while (*c < 32) __nanosleep(32);
        }
        __threadfence();
        __syncthreads();
    }

    // ================= GEMM (round-12 config, unchanged) =================
    const uint32_t sm_u32 = (uint32_t)__cvta_generic_to_shared(sm);

    const uint8_t* gsrc[4];
    uint32_t soff[4];
#pragma unroll
    for (int i = 0; i < 4; i++) {
        int c = tid + 256 * i;                // 0..1023
        if (c < BM * 8) {                     // A chunk
            int row = c >> 3, cc = c & 7;
            gsrc[i] = g_x8 + (size_t)(bm + row) * KDIM + cc * 16;
            soff[i] = (uint32_t)(row * ROWB + cc * 16);
        } else {                              // B chunk
            int cb = c - BM * 8;
            int row = cb >> 3, cc = cb & 7;
            gsrc[i] = g_w8 + (size_t)(bn + row) * KDIM + cc * 16;
            soff[i] = (uint32_t)(BM * ROWB + row * ROWB + cc * 16);
        }
    }
    auto load_stage = [&](int s, int kb) {
        uint32_t base = sm_u32 + (uint32_t)(s * STAGE_BYTES);
        uint32_t koff = (uint32_t)kb << 7;    // kb * 128 bytes
#pragma unroll
        for (int i = 0; i < 4; i++)
            cp_async16(base + soff[i], gsrc[i] + koff);
    };

    float master[4][4];
#pragma unroll
    for (int j = 0; j < 4; j++)
#pragma unroll
        for (int l = 0; l < 4; l++) master[j][l] = 0.f;

    load_stage(0, 0); cp_commit();
    load_stage(1, 1); cp_commit();
    load_stage(2, 2); cp_commit();

    const int la_row  = lane & 15;
    const int la_half = lane >> 4;
    const int lb_row  = ((lane >> 4) << 3) + (lane & 7);
    const int lb_half = (lane >> 3) & 1;
    const uint32_t aBase = (uint32_t)((wm + la_row) * ROWB + la_half * 16);
    const uint32_t bBase0 = (uint32_t)(BM * ROWB + (wn + lb_row) * ROWB + lb_half * 16);
    const uint32_t bBase1 = bBase0 + 16u * ROWB;
    const int gr = lane >> 2;

    const float* psa0 = g_sa + (size_t)(bm + wm + gr) * KB;   // rows c0,c1
    const float* psa1 = psa0 + 8 * KB;                        // rows c2,c3
    const float* psw  = sinv + (size_t)(bn >> 7) * KB;

    for (int kb = 0; kb < KB; kb++) {
        int rem = KB - 1 - kb;
        if (rem >= 2)      cp_wait<2>();
        else if (rem == 1) cp_wait<1>();
        else               cp_wait<0>();
        __syncthreads();
        if (kb + 3 < KB) { load_stage((kb + 3) & 3, kb + 3); cp_commit(); }

        const uint32_t st = sm_u32 + (uint32_t)((kb & 3) * STAGE_BYTES);

        float part[4][4];
#pragma unroll
        for (int j = 0; j < 4; j++)
#pragma unroll
            for (int l = 0; l < 4; l++) part[j][l] = 0.f;

#pragma unroll
        for (int ks = 0; ks < 4; ks++) {      // four k32 steps in BK=128
            const uint32_t k0 = (uint32_t)(ks * 32);
            uint32_t a[4];
            ldm_x4(a[0], a[1], a[2], a[3], st + aBase + k0);
#pragma unroll
            for (int p = 0; p < 2; p++) {
                uint32_t b[4];
                ldm_x4(b[0], b[1], b[2], b[3],
                       st + (p ? bBase1 : bBase0) + k0);
                mma_fp8(part[2 * p + 0], a, b + 0);
                mma_fp8(part[2 * p + 1], a, b + 2);
            }
        }

        float swk = __ldg(psw + kb);
        float f0 = __ldg(psa0 + kb) * swk;    // acc rows c0,c1
        float f1 = __ldg(psa1 + kb) * swk;    // acc rows c2,c3
#pragma unroll
        for (int nt = 0; nt < 4; nt++) {
            master[nt][0] += part[nt][0] * f0;
            master[nt][1] += part[nt][1] * f0;
            master[nt][2] += part[nt][2] * f1;
            master[nt][3] += part[nt][3] * f1;
        }
    }

    const int gid = lane >> 2, tig = lane & 3;
#pragma unroll
    for (int nt = 0; nt < 4; nt++) {
        int row = bm + wm + gid;
        int col = bn + wn + nt * 8 + tig * 2;
        float2 v01 = make_float2(bf16_round(master[nt][0]), bf16_round(master[nt][1]));
        *(float2*)&C[(size_t)row * NDIM + col] = v01;
        float2 v23 = make_float2(bf16_round(master[nt][2]), bf16_round(master[nt][3]));
        *(float2*)&C[(size_t)(row + 8) * NDIM + col] = v23;
    }
}

// ---------------------------------------------------------------------------
// Inputs identified BY ELEMENT COUNT: x 33554432, weight 4194304, sinv 256.
// ---------------------------------------------------------------------------
extern "C" void kernel_launch(void* const* d_in, const int* in_sizes, int n_in,
                              void* d_out, int out_size) {
    const float* x = nullptr; const float* w = nullptr; const float* sinv = nullptr;
    for (int i = 0; i < n_in; i++) {
        long long sz = in_sizes[i];
        if (sz == (long long)MDIM * KDIM)      x    = (const float*)d_in[i];
        else if (sz == (long long)NDIM * KDIM) w    = (const float*)d_in[i];
        else                                   sinv = (const float*)d_in[i];
    }
    if (!x)    x    = (const float*)d_in[0];
    if (!w)    w    = (const float*)d_in[1];
    if (!sinv) sinv = (const float*)d_in[2];
    float* out = (float*)d_out;

    // 1) weight quant + counter reset (serial, ~4us)
    quant_w_reset_kernel<<<1024, 256>>>(w);

    // 2) fused distributed A-quant + GEMM
    cudaFuncSetAttribute(gemm_kernel, cudaFuncAttributeMaxDynamicSharedMemorySize, SMEM_TOTAL);
    dim3 grid(NDIM / BN, MDIM / BM);               // (32, 256)
    gemm_kernel<<<grid, 256, SMEM_TOTAL>>>(out, sinv, x);
}